// round 13
// baseline (speedup 1.0000x reference)
#include <cuda_runtime.h>
#include <cuda_fp16.h>
#include <cstdint>

#define DEV_INLINE __device__ __forceinline__

constexpr int BB   = 8;
constexpr int LQ   = 10000;
constexpr int CDIM = 256;
constexpr int NHD  = 8;
constexpr int NPT  = 4;
constexpr int DFF  = 1024;
constexpr int HIMG = 100;
constexpr int WIMG = 100;
constexpr int HD   = 32;
constexpr int MTOK = BB * LQ;  // 80000
constexpr int NOFFAW = 96;

// fp16 activations
__device__ __half g_src_h  [MTOK * CDIM];
__device__ __half g_query_h[MTOK * CDIM];
__device__ __half g_value_h[MTOK * CDIM];
__device__ __half g_attn_h [MTOK * CDIM];
__device__ __half g_q2_h   [MTOK * CDIM];
__device__ __half g_ffn_h  [MTOK * DFF];
// fp32 buffers
__device__ float g_offaw[MTOK * NOFFAW];
// fp16 transposed weights [N][K]
__device__ __half g_WvalT[CDIM * CDIM];
__device__ __half g_WoutT[CDIM * CDIM];
__device__ __half g_W1T  [DFF * CDIM];
__device__ __half g_W2T  [CDIM * DFF];
__device__ __half g_WcatT[128 * CDIM];
__device__ float  g_bcat [128];

// ---------------------------------------------------------------------------
// MMA / ldmatrix helpers
// ---------------------------------------------------------------------------
DEV_INLINE void mma_f16(float* d, const uint32_t* a, const uint32_t* b) {
    asm volatile(
        "mma.sync.aligned.m16n8k16.row.col.f32.f16.f16.f32 "
        "{%0,%1,%2,%3}, {%4,%5,%6,%7}, {%8,%9}, {%0,%1,%2,%3};\n"
        : "+f"(d[0]), "+f"(d[1]), "+f"(d[2]), "+f"(d[3])
        : "r"(a[0]), "r"(a[1]), "r"(a[2]), "r"(a[3]), "r"(b[0]), "r"(b[1]));
}

DEV_INLINE void ldsm_x4(uint32_t* r, uint32_t addr) {
    asm volatile("ldmatrix.sync.aligned.m8n8.x4.shared.b16 {%0,%1,%2,%3}, [%4];"
                 : "=r"(r[0]), "=r"(r[1]), "=r"(r[2]), "=r"(r[3]) : "r"(addr));
}

DEV_INLINE void cp_async16(uint32_t dst, const void* src) {
    asm volatile("cp.async.cg.shared.global [%0], [%1], 16;\n" :: "r"(dst), "l"(src));
}

// ---------------------------------------------------------------------------
// fp16 tensor-core GEMM: acc = A[M,K] @ BT[N,K]^T  (rows offset by mrow0)
// MODE 0: f32 out      MODE 1: fp16 out
// MODE 2: LN, residual f32, writes fp16 out16 only     (W_out + LN1 -> q2_h)
// MODE 3: LN, residual fp16 (cast of resid), writes f32 Cv only (FFN2 + LN2)
// ---------------------------------------------------------------------------
constexpr int BM = 128, BK = 32;

template<int BN_, int MODE, int STG>
__global__ __launch_bounds__(256, (BN_ <= 128) ? 2 : 1) void gemm_h_kernel(
    const __half* __restrict__ A, const __half* __restrict__ BT,
    const float* __restrict__ bias, void* __restrict__ Cv,
    int N, int K, int relu,
    const float* __restrict__ resid, const float* __restrict__ gam,
    const float* __restrict__ bet, __half* __restrict__ out16,
    int mrow0)
{
    constexpr int WNT = BN_ / 4;
    constexpr int NI  = WNT / 8;
    constexpr int A_BYTES = BM * 64;
    constexpr int B_BYTES = BN_ * 64;
    constexpr int STAGE_BYTES = A_BYTES + B_BYTES;
    constexpr bool LN = (MODE >= 2);

    extern __shared__ char dsm[];
    uint32_t sm0 = (uint32_t)__cvta_generic_to_shared(dsm);

    __shared__ float s_bias[BN_];
    __shared__ float s_red[LN ? 128 : 1][8];
    __shared__ float s_g[LN ? 256 : 1], s_b[LN ? 256 : 1];

    const int tid  = threadIdx.x;
    const int lane = tid & 31;
    const int wid  = tid >> 5;
    const int wm   = wid >> 2;
    const int wn   = wid & 3;
    const size_t mbase = (size_t)mrow0 + (size_t)blockIdx.y * BM;
    const int    nbase = blockIdx.x * BN_;

    const int g  = lane >> 3;
    const int rr = lane & 7;

    const int rowA = wm * 64 + rr + (g & 1) * 8;
    const uint32_t swA = (uint32_t)((rowA >> 1) & 3);
    const uint32_t aoff[2] = { (((0u + (g >> 1)) ^ swA) << 4),
                               (((2u + (g >> 1)) ^ swA) << 4) };
    const uint32_t aBase = (uint32_t)rowA * 64u;

    const int rowB = wn * WNT + rr + (g >> 1) * 8;
    const uint32_t swB = (uint32_t)((rowB >> 1) & 3);
    const uint32_t boff[2] = { (((0u + (g & 1)) ^ swB) << 4),
                               (((2u + (g & 1)) ^ swB) << 4) };
    const uint32_t bBase = (uint32_t)rowB * 64u;

    const int arow = tid >> 1;
    const int ac   = tid & 1;
    const __half* Ab = A + mbase * (size_t)K;

    for (int c = tid; c < BN_; c += 256) s_bias[c] = bias[nbase + c];

    float acc[4][NI][4];
#pragma unroll
    for (int mi = 0; mi < 4; ++mi)
#pragma unroll
        for (int ni = 0; ni < NI; ++ni)
#pragma unroll
            for (int j = 0; j < 4; ++j) acc[mi][ni][j] = 0.f;

    auto load_tile = [&](int stage, int k0) {
        uint32_t sA = sm0 + stage * STAGE_BYTES;
        uint32_t sB = sA + A_BYTES;
#pragma unroll
        for (int i = 0; i < 2; ++i) {
            int c = ac * 2 + i;
            cp_async16(sA + arow * 64 + ((c ^ ((arow >> 1) & 3)) << 4),
                       Ab + (size_t)arow * K + k0 + c * 8);
        }
#pragma unroll
        for (int it = 0; it < BN_ / 64; ++it) {
            int idx = tid + it * 256;
            int row = idx >> 2, c = idx & 3;
            cp_async16(sB + row * 64 + ((c ^ ((row >> 1) & 3)) << 4),
                       BT + (size_t)(nbase + row) * K + k0 + c * 8);
        }
    };

    const int ntiles = K / BK;

#pragma unroll
    for (int s = 0; s < STG - 1; ++s) {
        if (s < ntiles) load_tile(s, s * BK);
        asm volatile("cp.async.commit_group;\n");
    }
    asm volatile("cp.async.wait_group %0;\n" :: "n"(STG - 2));
    __syncthreads();

    int read_stage = 0, write_stage = STG - 1;

    for (int i = 0; i < ntiles; ++i) {
        uint32_t sA = sm0 + read_stage * STAGE_BYTES;
        uint32_t sB = sA + A_BYTES;

#pragma unroll
        for (int ks = 0; ks < 2; ++ks) {
            uint32_t afr[4][4], bfr[NI / 2][4];
#pragma unroll
            for (int mi = 0; mi < 4; ++mi)
                ldsm_x4(afr[mi], sA + aBase + mi * 1024 + aoff[ks]);
#pragma unroll
            for (int p = 0; p < NI / 2; ++p)
                ldsm_x4(bfr[p], sB + bBase + p * 1024 + boff[ks]);
#pragma unroll
            for (int mi = 0; mi < 4; ++mi)
#pragma unroll
                for (int ni = 0; ni < NI; ++ni)
                    mma_f16(acc[mi][ni], afr[mi], &bfr[ni >> 1][(ni & 1) * 2]);
        }

        if (i + STG - 1 < ntiles)
            load_tile(write_stage, (i + STG - 1) * BK);
        asm volatile("cp.async.commit_group;\n");
        asm volatile("cp.async.wait_group %0;\n" :: "n"(STG - 2));
        __syncthreads();

        if (++read_stage == STG)  read_stage = 0;
        if (++write_stage == STG) write_stage = 0;
    }

    if (LN) {
        const __half* residH = (const __half*)resid;
#pragma unroll
        for (int mi = 0; mi < 4; ++mi) {
            float psum0 = 0.f, psq0 = 0.f, psum1 = 0.f, psq1 = 0.f;
            size_t r0 = mbase + wm * 64 + mi * 16 + (lane >> 2);
            size_t r1 = r0 + 8;
#pragma unroll
            for (int ni = 0; ni < NI; ++ni) {
                int col = wn * WNT + ni * 8 + (lane & 3) * 2;
                float b0 = s_bias[col], b1 = s_bias[col + 1];
                float2 x0, x1;
                if (MODE == 3) {
                    x0 = __half22float2(*(const __half2*)(residH + r0 * 256 + col));
                    x1 = __half22float2(*(const __half2*)(residH + r1 * 256 + col));
                } else {
                    x0 = *(const float2*)(resid + r0 * 256 + col);
                    x1 = *(const float2*)(resid + r1 * 256 + col);
                }
                float v0 = acc[mi][ni][0] + b0 + x0.x;
                float v1 = acc[mi][ni][1] + b1 + x0.y;
                float v2 = acc[mi][ni][2] + b0 + x1.x;
                float v3 = acc[mi][ni][3] + b1 + x1.y;
                acc[mi][ni][0] = v0; acc[mi][ni][1] = v1;
                acc[mi][ni][2] = v2; acc[mi][ni][3] = v3;
                psum0 += v0 + v1; psq0 += v0 * v0 + v1 * v1;
                psum1 += v2 + v3; psq1 += v2 * v2 + v3 * v3;
            }
#pragma unroll
            for (int o = 1; o <= 2; o <<= 1) {
                psum0 += __shfl_xor_sync(0xffffffffu, psum0, o);
                psq0  += __shfl_xor_sync(0xffffffffu, psq0,  o);
                psum1 += __shfl_xor_sync(0xffffffffu, psum1, o);
                psq1  += __shfl_xor_sync(0xffffffffu, psq1,  o);
            }
            if ((lane & 3) == 0) {
                int rl = wm * 64 + mi * 16 + (lane >> 2);
                s_red[rl][wn * 2] = psum0;     s_red[rl][wn * 2 + 1] = psq0;
                s_red[rl + 8][wn * 2] = psum1; s_red[rl + 8][wn * 2 + 1] = psq1;
            }
        }
        s_g[tid] = gam[tid];
        s_b[tid] = bet[tid];
        __syncthreads();

        float mstat[4][2][2];
#pragma unroll
        for (int mi = 0; mi < 4; ++mi) {
#pragma unroll
            for (int hh = 0; hh < 2; ++hh) {
                int rl = wm * 64 + mi * 16 + (lane >> 2) + hh * 8;
                float su = s_red[rl][0] + s_red[rl][2] + s_red[rl][4] + s_red[rl][6];
                float sq = s_red[rl][1] + s_red[rl][3] + s_red[rl][5] + s_red[rl][7];
                float m = su * (1.0f / 256);
                mstat[mi][hh][0] = m;
                mstat[mi][hh][1] = rsqrtf(sq * (1.0f / 256) - m * m + 1e-5f);
            }
        }

        float* C = (float*)Cv;
#pragma unroll
        for (int mi = 0; mi < 4; ++mi) {
            size_t r0 = mbase + wm * 64 + mi * 16 + (lane >> 2);
            size_t r1 = r0 + 8;
            float m0 = mstat[mi][0][0], s0 = mstat[mi][0][1];
            float m1 = mstat[mi][1][0], s1 = mstat[mi][1][1];
#pragma unroll
            for (int ni = 0; ni < NI; ++ni) {
                int col = wn * WNT + ni * 8 + (lane & 3) * 2;
                float g0 = s_g[col], g1v = s_g[col + 1];
                float be0 = s_b[col], be1 = s_b[col + 1];
                float o0 = (acc[mi][ni][0] - m0) * s0 * g0  + be0;
                float o1 = (acc[mi][ni][1] - m0) * s0 * g1v + be1;
                float o2 = (acc[mi][ni][2] - m1) * s1 * g0  + be0;
                float o3 = (acc[mi][ni][3] - m1) * s1 * g1v + be1;
                if (MODE == 2) {
                    *(__half2*)(out16 + r0 * 256 + col) = __floats2half2_rn(o0, o1);
                    *(__half2*)(out16 + r1 * 256 + col) = __floats2half2_rn(o2, o3);
                } else {
                    *(float2*)(C + r0 * 256 + col) = make_float2(o0, o1);
                    *(float2*)(C + r1 * 256 + col) = make_float2(o2, o3);
                }
            }
        }
        return;
    }

#pragma unroll
    for (int mi = 0; mi < 4; ++mi) {
#pragma unroll
        for (int ni = 0; ni < NI; ++ni) {
            int col = nbase + wn * WNT + ni * 8 + (lane & 3) * 2;
            if (col >= N) continue;
            size_t r0 = mbase + wm * 64 + mi * 16 + (lane >> 2);
            size_t r1 = r0 + 8;
            float b0 = s_bias[col - nbase];
            float b1 = s_bias[col - nbase + 1];
            float v0 = acc[mi][ni][0] + b0;
            float v1 = acc[mi][ni][1] + b1;
            float v2 = acc[mi][ni][2] + b0;
            float v3 = acc[mi][ni][3] + b1;
            if (relu) {
                v0 = fmaxf(v0, 0.f); v1 = fmaxf(v1, 0.f);
                v2 = fmaxf(v2, 0.f); v3 = fmaxf(v3, 0.f);
            }
            if (MODE == 1) {
                __half* C = (__half*)Cv;
                *(__half2*)(C + r0 * (size_t)N + col) = __floats2half2_rn(v0, v1);
                *(__half2*)(C + r1 * (size_t)N + col) = __floats2half2_rn(v2, v3);
            } else {
                float* C = (float*)Cv;
                C[r0 * (size_t)N + col]     = v0;
                C[r0 * (size_t)N + col + 1] = v1;
                C[r1 * (size_t)N + col]     = v2;
                C[r1 * (size_t)N + col + 1] = v3;
            }
        }
    }
}

constexpr int SMEM_128_3 = 3 * (BM * 64 + 128 * 64);  // 49152
constexpr int SMEM_256_4 = 4 * (BM * 64 + 256 * 64);  // 98304

// ---------------------------------------------------------------------------
// prep kernels
// ---------------------------------------------------------------------------
__global__ void f2h_kernel(const float* __restrict__ in, __half* __restrict__ out,
                           long n)
{
    long i = ((long)blockIdx.x * blockDim.x + threadIdx.x) * 4;
    if (i < n) {
        float4 v = *(const float4*)(in + i);
        *(__half2*)(out + i)     = __floats2half2_rn(v.x, v.y);
        *(__half2*)(out + i + 2) = __floats2half2_rn(v.z, v.w);
    }
}

__global__ void transpose_h_kernel(const float* __restrict__ in,
                                   __half* __restrict__ out, int K, int N)
{
    __shared__ float t[32][33];
    int k0 = blockIdx.y * 32, n0 = blockIdx.x * 32;
    int x = threadIdx.x, y = threadIdx.y;
#pragma unroll
    for (int i = y; i < 32; i += 8)
        t[i][x] = in[(size_t)(k0 + i) * N + n0 + x];
    __syncthreads();
#pragma unroll
    for (int i = y; i < 32; i += 8)
        out[(size_t)(n0 + i) * K + k0 + x] = __float2half(t[x][i]);
}

__global__ void concat_t_kernel(const float* __restrict__ W_off,
                                const float* __restrict__ b_off,
                                const float* __restrict__ W_aw,
                                const float* __restrict__ b_aw)
{
    int i = blockIdx.x * blockDim.x + threadIdx.x;
    if (i < 128 * CDIM) {
        int n = i / CDIM, k = i % CDIM;
        float v = 0.f;
        if (n < 64)       v = W_off[k * 64 + n];
        else if (n < 96)  v = W_aw[k * 32 + (n - 64)];
        g_WcatT[i] = __float2half(v);
    }
    if (i < 128)
        g_bcat[i] = (i < 64) ? b_off[i] : (i < 96 ? b_aw[i - 64] : 0.f);
}

// ---------------------------------------------------------------------------
// Bilinear sampling: 8 tokens/block, each thread handles 2 tokens (ILP x2).
// ---------------------------------------------------------------------------
__global__ __launch_bounds__(256) void sample_kernel(
    const float* __restrict__ refp, __half* __restrict__ attn, long tokbase)
{
    __shared__ float s_oa[8][NOFFAW];
    __shared__ float2 s_ref[8];

    const int tid = threadIdx.x;
    const int lt  = tid >> 6;
    const int t64 = tid & 63;
    const int h   = t64 >> 3;
    const int l8  = t64 & 7;
    const long tok0 = tokbase + (long)blockIdx.x * 8;

    if (tid < 192) {
        int ltt = tid / 24, e = (tid % 24) * 4;
        *(float4*)&s_oa[ltt][e] =
            *(const float4*)(g_offaw + (tok0 + ltt) * NOFFAW + e);
    } else if (tid < 200) {
        int j = tid - 192;
        s_ref[j] = ((const float2*)refp)[tok0 + j];
    }
    __syncthreads();

    float4 accT[2];
    const float* oaT[2];
    float awwT[2][4];
    const __half* vbT[2];

#pragma unroll
    for (int u = 0; u < 2; ++u) {
        const int sl = lt + u * 4;
        const long token = tok0 + sl;
        const int b = (int)(token / LQ);
        oaT[u] = s_oa[sl];
        const float* oa = oaT[u];
        float l0 = oa[64 + h * 4 + 0], l1 = oa[64 + h * 4 + 1];
        float l2 = oa[64 + h * 4 + 2], l3 = oa[64 + h * 4 + 3];
        float mx = fmaxf(fmaxf(l0, l1), fmaxf(l2, l3));
        float e0 = __expf(l0 - mx), e1 = __expf(l1 - mx);
        float e2 = __expf(l2 - mx), e3 = __expf(l3 - mx);
        float inv = 1.f / (e0 + e1 + e2 + e3);
        awwT[u][0] = e0 * inv; awwT[u][1] = e1 * inv;
        awwT[u][2] = e2 * inv; awwT[u][3] = e3 * inv;
        vbT[u] = g_value_h + ((size_t)b * LQ) * CDIM + h * HD + l8 * 4;
        accT[u] = make_float4(0.f, 0.f, 0.f, 0.f);
    }

#pragma unroll
    for (int p = 0; p < NPT; ++p) {
        float wgt[2][4];
        int xsv[2][4], ysv[2][4];
#pragma unroll
        for (int u = 0; u < 2; ++u) {
            const int sl = lt + u * 4;
            float rx = s_ref[sl].x, ry = s_ref[sl].y;
            float x = rx * WIMG + oaT[u][(h * NPT + p) * 2 + 0] - 0.5f;
            float y = ry * HIMG + oaT[u][(h * NPT + p) * 2 + 1] - 0.5f;
            float x0f = floorf(x), y0f = floorf(y);
            float fx = x - x0f, fy = y - y0f;
            int x0 = (int)x0f, y0 = (int)y0f;
            float a = awwT[u][p];
            wgt[u][0] = a * (1.f - fx) * (1.f - fy);
            wgt[u][1] = a * fx * (1.f - fy);
            wgt[u][2] = a * (1.f - fx) * fy;
            wgt[u][3] = a * fx * fy;
            xsv[u][0] = x0; xsv[u][1] = x0 + 1; xsv[u][2] = x0;     xsv[u][3] = x0 + 1;
            ysv[u][0] = y0; ysv[u][1] = y0;     ysv[u][2] = y0 + 1; ysv[u][3] = y0 + 1;
        }
#pragma unroll
        for (int c = 0; c < 4; ++c) {
#pragma unroll
            for (int u = 0; u < 2; ++u) {
                int xi = xsv[u][c], yi = ysv[u][c];
                float w = wgt[u][c];
                if (xi >= 0 && xi < WIMG && yi >= 0 && yi < HIMG && w != 0.f) {
                    const __half2* vp =
                        (const __half2*)(vbT[u] + (size_t)(yi * WIMG + xi) * CDIM);
                    float2 u0 = __half22float2(vp[0]);
                    float2 u1 = __half22float2(vp[1]);
                    accT[u].x += u0.x * w; accT[u].y += u0.y * w;
                    accT[u].z += u1.x * w; accT[u].w += u1.y * w;
                }
            }
        }
    }

#pragma unroll
    for (int u = 0; u < 2; ++u) {
        const long token = tok0 + lt + u * 4;
        __half* dst = attn + (size_t)token * CDIM + h * HD + l8 * 4;
        *(__half2*)(dst)     = __floats2half2_rn(accT[u].x, accT[u].y);
        *(__half2*)(dst + 2) = __floats2half2_rn(accT[u].z, accT[u].w);
    }
}

// ---------------------------------------------------------------------------
// Launch: two-stream prep overlap + 4-chunk pipelined back half
// ---------------------------------------------------------------------------
extern "C" void kernel_launch(void* const* d_in, const int* in_sizes, int n_in,
                              void* d_out, int out_size)
{
    const float* query = (const float*)d_in[0];
    const float* src   = (const float*)d_in[1];
    const float* refp  = (const float*)d_in[2];
    const float* W_off = (const float*)d_in[5];
    const float* b_off = (const float*)d_in[6];
    const float* W_aw  = (const float*)d_in[7];
    const float* b_aw  = (const float*)d_in[8];
    const float* W_val = (const float*)d_in[9];
    const float* b_val = (const float*)d_in[10];
    const float* W_out = (const float*)d_in[11];
    const float* b_out = (const float*)d_in[12];
    const float* g1    = (const float*)d_in[13];
    const float* be1   = (const float*)d_in[14];
    const float* W1    = (const float*)d_in[15];
    const float* b1    = (const float*)d_in[16];
    const float* W2    = (const float*)d_in[17];
    const float* b2    = (const float*)d_in[18];
    const float* g2    = (const float*)d_in[19];
    const float* be2   = (const float*)d_in[20];
    float* out = (float*)d_out;

    __half *p_src_h, *p_query_h, *p_value_h, *p_attn_h, *p_q2_h, *p_ffn_h;
    __half *p_WvalT, *p_WoutT, *p_W1T, *p_W2T, *p_WcatT;
    float *p_offaw, *p_bcat;
    cudaGetSymbolAddress((void**)&p_src_h,   g_src_h);
    cudaGetSymbolAddress((void**)&p_query_h, g_query_h);
    cudaGetSymbolAddress((void**)&p_value_h, g_value_h);
    cudaGetSymbolAddress((void**)&p_attn_h,  g_attn_h);
    cudaGetSymbolAddress((void**)&p_q2_h,    g_q2_h);
    cudaGetSymbolAddress((void**)&p_ffn_h,   g_ffn_h);
    cudaGetSymbolAddress((void**)&p_offaw,   g_offaw);
    cudaGetSymbolAddress((void**)&p_WvalT,   g_WvalT);
    cudaGetSymbolAddress((void**)&p_WoutT,   g_WoutT);
    cudaGetSymbolAddress((void**)&p_W1T,     g_W1T);
    cudaGetSymbolAddress((void**)&p_W2T,     g_W2T);
    cudaGetSymbolAddress((void**)&p_WcatT,   g_WcatT);
    cudaGetSymbolAddress((void**)&p_bcat,    g_bcat);

    static cudaStream_t s1 = nullptr;
    static cudaEvent_t evFork = nullptr, evB = nullptr, evC = nullptr,
                       evSrc = nullptr, evVal0 = nullptr, evVal1 = nullptr,
                       evD = nullptr;
    static bool attr_done = false;
    if (!s1) {
        cudaStreamCreateWithFlags(&s1, cudaStreamNonBlocking);
        cudaEventCreateWithFlags(&evFork, cudaEventDisableTiming);
        cudaEventCreateWithFlags(&evB,    cudaEventDisableTiming);
        cudaEventCreateWithFlags(&evC,    cudaEventDisableTiming);
        cudaEventCreateWithFlags(&evSrc,  cudaEventDisableTiming);
        cudaEventCreateWithFlags(&evVal0, cudaEventDisableTiming);
        cudaEventCreateWithFlags(&evVal1, cudaEventDisableTiming);
        cudaEventCreateWithFlags(&evD,    cudaEventDisableTiming);
    }
    if (!attr_done) {
        cudaFuncSetAttribute(gemm_h_kernel<128, 0, 3>,
                             cudaFuncAttributeMaxDynamicSharedMemorySize, SMEM_128_3);
        cudaFuncSetAttribute(gemm_h_kernel<128, 1, 3>,
                             cudaFuncAttributeMaxDynamicSharedMemorySize, SMEM_128_3);
        cudaFuncSetAttribute(gemm_h_kernel<256, 2, 4>,
                             cudaFuncAttributeMaxDynamicSharedMemorySize, SMEM_256_4);
        cudaFuncSetAttribute(gemm_h_kernel<256, 3, 4>,
                             cudaFuncAttributeMaxDynamicSharedMemorySize, SMEM_256_4);
        attr_done = true;
    }

    dim3 tb(32, 8);
    const long NELT = (long)MTOK * CDIM;
    const int F2H_GRID = (int)((NELT / 4 + 255) / 256);

    // value GEMM split: P0 rows [0, 50048) on A (covers chunks 0-1, batches 0-4);
    // P1 rows [50048, 80000) on s1 (covers chunks 2-3).
    const int VAL_MB0 = 391, VAL_MB1 = 234;
    const int VAL_ROW1 = VAL_MB0 * BM;     // 50048

    // ---- fork ----
    cudaEventRecord(evFork, 0);
    cudaStreamWaitEvent(s1, evFork, 0);

    // stream B (s1): query-side chain + weight preps
    f2h_kernel<<<F2H_GRID, 256, 0, s1>>>(query, p_query_h, NELT);
    concat_t_kernel<<<(128 * CDIM + 255) / 256, 256, 0, s1>>>(W_off, b_off, W_aw, b_aw);
    gemm_h_kernel<128, 0, 3><<<dim3(1, MTOK / BM), 256, SMEM_128_3, s1>>>(
        p_query_h, p_WcatT, p_bcat, p_offaw, NOFFAW, CDIM, 0,
        nullptr, nullptr, nullptr, nullptr, 0);
    cudaEventRecord(evB, s1);
    transpose_h_kernel<<<dim3(CDIM / 32, CDIM / 32), tb, 0, s1>>>(W_out, p_WoutT, CDIM, CDIM);
    transpose_h_kernel<<<dim3(DFF / 32,  CDIM / 32), tb, 0, s1>>>(W1, p_W1T, CDIM, DFF);
    transpose_h_kernel<<<dim3(CDIM / 32, DFF / 32),  tb, 0, s1>>>(W2, p_W2T, DFF, CDIM);
    cudaEventRecord(evC, s1);

    // stream A (default): src-side chain -> value P0
    f2h_kernel<<<F2H_GRID, 256>>>(src, p_src_h, NELT);
    transpose_h_kernel<<<dim3(CDIM / 32, CDIM / 32), tb>>>(W_val, p_WvalT, CDIM, CDIM);
    cudaEventRecord(evSrc, 0);
    gemm_h_kernel<128, 1, 3><<<dim3(2, VAL_MB0), 256, SMEM_128_3>>>(
        p_src_h, p_WvalT, b_val, p_value_h, CDIM, CDIM, 0,
        nullptr, nullptr, nullptr, nullptr, 0);
    cudaEventRecord(evVal0, 0);

    // value P1 on s1 (after src_h/WvalT ready)
    cudaStreamWaitEvent(s1, evSrc, 0);
    gemm_h_kernel<128, 1, 3><<<dim3(2, VAL_MB1), 256, SMEM_128_3, s1>>>(
        p_src_h, p_WvalT, b_val, p_value_h, CDIM, CDIM, 0,
        nullptr, nullptr, nullptr, nullptr, VAL_ROW1);
    cudaEventRecord(evVal1, s1);

    // ---- back half: 4 row-chunks pipelined across the two streams ----
    // chunks: 157,156,156,156 blocks; A runs chunks 0,2; s1 runs chunks 1,3.
    const int MBc[4]  = {157, 156, 156, 156};
    const int ROWc[4] = {0, 157 * BM, 313 * BM, 469 * BM};
    cudaStream_t st[4] = {(cudaStream_t)0, s1, (cudaStream_t)0, s1};

    // deps:
    //  chunk0 (A): value P0 sequenced on A; needs offaw/weights (evB, evC).
    //  chunk1 (s1): needs value P0 (evVal0); weights sequenced on s1.
    //  chunk2 (A): tokens < 60032 -> batches <= 6 -> needs value P1 (evVal1).
    //  chunk3 (s1): P1 sequenced on s1; P0 via earlier evVal0 wait.
    cudaStreamWaitEvent(0, evB, 0);
    cudaStreamWaitEvent(0, evC, 0);
    cudaStreamWaitEvent(s1, evVal0, 0);

    for (int c = 0; c < 4; ++c) {
        cudaStream_t s = st[c];
        const int mb = MBc[c], row0 = ROWc[c];
        if (c == 2) cudaStreamWaitEvent(0, evVal1, 0);
        sample_kernel<<<mb * BM / 8, 256, 0, s>>>(refp, p_attn_h, row0);
        // W_out + residual(query f32) + LN1 -> q2_h (fp16 only)
        gemm_h_kernel<256, 2, 4><<<dim3(1, mb), 256, SMEM_256_4, s>>>(
            p_attn_h, p_WoutT, b_out, nullptr, CDIM, CDIM, 0,
            query, g1, be1, p_q2_h, row0);
        // FFN1 (relu, fp16 out)
        gemm_h_kernel<128, 1, 3><<<dim3(DFF / 128, mb), 256, SMEM_128_3, s>>>(
            p_q2_h, p_W1T, b1, p_ffn_h, DFF, CDIM, 1,
            nullptr, nullptr, nullptr, nullptr, row0);
        // FFN2 + residual(q2_h fp16) + LN2 -> final f32 out
        gemm_h_kernel<256, 3, 4><<<dim3(1, mb), 256, SMEM_256_4, s>>>(
            p_ffn_h, p_W2T, b2, out, CDIM, DFF, 0,
            (const float*)p_q2_h, g2, be2, nullptr, row0);
    }

    // join s1 back to the origin stream (capture requires it)
    cudaEventRecord(evD, s1);
    cudaStreamWaitEvent(0, evD, 0);
}

// round 14
// speedup vs baseline: 1.0568x; 1.0568x over previous
#include <cuda_runtime.h>
#include <cuda_fp16.h>
#include <cstdint>

#define DEV_INLINE __device__ __forceinline__

constexpr int BB   = 8;
constexpr int LQ   = 10000;
constexpr int CDIM = 256;
constexpr int NHD  = 8;
constexpr int NPT  = 4;
constexpr int DFF  = 1024;
constexpr int HIMG = 100;
constexpr int WIMG = 100;
constexpr int HD   = 32;
constexpr int MTOK = BB * LQ;  // 80000
constexpr int NOFFAW = 96;

// fp16 activations
__device__ __half g_src_h  [MTOK * CDIM];
__device__ __half g_query_h[MTOK * CDIM];
__device__ __half g_value_h[MTOK * CDIM];
__device__ __half g_attn_h [MTOK * CDIM];
__device__ __half g_q2_h   [MTOK * CDIM];
__device__ __half g_ffn_h  [MTOK * DFF];
// fp32 buffers
__device__ float g_offaw[MTOK * NOFFAW];
// fp16 transposed weights [N][K]
__device__ __half g_WvalT[CDIM * CDIM];
__device__ __half g_WoutT[CDIM * CDIM];
__device__ __half g_W1T  [DFF * CDIM];
__device__ __half g_W2T  [CDIM * DFF];
__device__ __half g_WcatT[128 * CDIM];
__device__ float  g_bcat [128];

// ---------------------------------------------------------------------------
// MMA / ldmatrix helpers
// ---------------------------------------------------------------------------
DEV_INLINE void mma_f16(float* d, const uint32_t* a, const uint32_t* b) {
    asm volatile(
        "mma.sync.aligned.m16n8k16.row.col.f32.f16.f16.f32 "
        "{%0,%1,%2,%3}, {%4,%5,%6,%7}, {%8,%9}, {%0,%1,%2,%3};\n"
        : "+f"(d[0]), "+f"(d[1]), "+f"(d[2]), "+f"(d[3])
        : "r"(a[0]), "r"(a[1]), "r"(a[2]), "r"(a[3]), "r"(b[0]), "r"(b[1]));
}

DEV_INLINE void ldsm_x4(uint32_t* r, uint32_t addr) {
    asm volatile("ldmatrix.sync.aligned.m8n8.x4.shared.b16 {%0,%1,%2,%3}, [%4];"
                 : "=r"(r[0]), "=r"(r[1]), "=r"(r[2]), "=r"(r[3]) : "r"(addr));
}

DEV_INLINE void cp_async16(uint32_t dst, const void* src) {
    asm volatile("cp.async.cg.shared.global [%0], [%1], 16;\n" :: "r"(dst), "l"(src));
}

// ---------------------------------------------------------------------------
// fp16 tensor-core GEMM: acc = A[M,K] @ BT[N,K]^T  (rows offset by mrow0)
// MODE 0: f32 out      MODE 1: fp16 out
// MODE 2: LN, residual f32, writes fp16 out16 only     (W_out + LN1 -> q2_h)
// MODE 3: LN, residual fp16 (cast of resid), writes f32 Cv only (FFN2 + LN2)
// ---------------------------------------------------------------------------
constexpr int BM = 128, BK = 32;

template<int BN_, int MODE, int STG>
__global__ __launch_bounds__(256, (BN_ <= 128) ? 2 : 1) void gemm_h_kernel(
    const __half* __restrict__ A, const __half* __restrict__ BT,
    const float* __restrict__ bias, void* __restrict__ Cv,
    int N, int K, int relu,
    const float* __restrict__ resid, const float* __restrict__ gam,
    const float* __restrict__ bet, __half* __restrict__ out16,
    int mrow0)
{
    constexpr int WNT = BN_ / 4;
    constexpr int NI  = WNT / 8;
    constexpr int A_BYTES = BM * 64;
    constexpr int B_BYTES = BN_ * 64;
    constexpr int STAGE_BYTES = A_BYTES + B_BYTES;
    constexpr bool LN = (MODE >= 2);

    extern __shared__ char dsm[];
    uint32_t sm0 = (uint32_t)__cvta_generic_to_shared(dsm);

    __shared__ float s_bias[BN_];
    __shared__ float s_red[LN ? 128 : 1][8];
    __shared__ float s_g[LN ? 256 : 1], s_b[LN ? 256 : 1];

    const int tid  = threadIdx.x;
    const int lane = tid & 31;
    const int wid  = tid >> 5;
    const int wm   = wid >> 2;
    const int wn   = wid & 3;
    const size_t mbase = (size_t)mrow0 + (size_t)blockIdx.y * BM;
    const int    nbase = blockIdx.x * BN_;

    const int g  = lane >> 3;
    const int rr = lane & 7;

    const int rowA = wm * 64 + rr + (g & 1) * 8;
    const uint32_t swA = (uint32_t)((rowA >> 1) & 3);
    const uint32_t aoff[2] = { (((0u + (g >> 1)) ^ swA) << 4),
                               (((2u + (g >> 1)) ^ swA) << 4) };
    const uint32_t aBase = (uint32_t)rowA * 64u;

    const int rowB = wn * WNT + rr + (g >> 1) * 8;
    const uint32_t swB = (uint32_t)((rowB >> 1) & 3);
    const uint32_t boff[2] = { (((0u + (g & 1)) ^ swB) << 4),
                               (((2u + (g & 1)) ^ swB) << 4) };
    const uint32_t bBase = (uint32_t)rowB * 64u;

    const int arow = tid >> 1;
    const int ac   = tid & 1;
    const __half* Ab = A + mbase * (size_t)K;

    for (int c = tid; c < BN_; c += 256) s_bias[c] = bias[nbase + c];

    float acc[4][NI][4];
#pragma unroll
    for (int mi = 0; mi < 4; ++mi)
#pragma unroll
        for (int ni = 0; ni < NI; ++ni)
#pragma unroll
            for (int j = 0; j < 4; ++j) acc[mi][ni][j] = 0.f;

    auto load_tile = [&](int stage, int k0) {
        uint32_t sA = sm0 + stage * STAGE_BYTES;
        uint32_t sB = sA + A_BYTES;
#pragma unroll
        for (int i = 0; i < 2; ++i) {
            int c = ac * 2 + i;
            cp_async16(sA + arow * 64 + ((c ^ ((arow >> 1) & 3)) << 4),
                       Ab + (size_t)arow * K + k0 + c * 8);
        }
#pragma unroll
        for (int it = 0; it < BN_ / 64; ++it) {
            int idx = tid + it * 256;
            int row = idx >> 2, c = idx & 3;
            cp_async16(sB + row * 64 + ((c ^ ((row >> 1) & 3)) << 4),
                       BT + (size_t)(nbase + row) * K + k0 + c * 8);
        }
    };

    const int ntiles = K / BK;

#pragma unroll
    for (int s = 0; s < STG - 1; ++s) {
        if (s < ntiles) load_tile(s, s * BK);
        asm volatile("cp.async.commit_group;\n");
    }
    asm volatile("cp.async.wait_group %0;\n" :: "n"(STG - 2));
    __syncthreads();

    int read_stage = 0, write_stage = STG - 1;

    for (int i = 0; i < ntiles; ++i) {
        uint32_t sA = sm0 + read_stage * STAGE_BYTES;
        uint32_t sB = sA + A_BYTES;

#pragma unroll
        for (int ks = 0; ks < 2; ++ks) {
            uint32_t afr[4][4], bfr[NI / 2][4];
#pragma unroll
            for (int mi = 0; mi < 4; ++mi)
                ldsm_x4(afr[mi], sA + aBase + mi * 1024 + aoff[ks]);
#pragma unroll
            for (int p = 0; p < NI / 2; ++p)
                ldsm_x4(bfr[p], sB + bBase + p * 1024 + boff[ks]);
#pragma unroll
            for (int mi = 0; mi < 4; ++mi)
#pragma unroll
                for (int ni = 0; ni < NI; ++ni)
                    mma_f16(acc[mi][ni], afr[mi], &bfr[ni >> 1][(ni & 1) * 2]);
        }

        if (i + STG - 1 < ntiles)
            load_tile(write_stage, (i + STG - 1) * BK);
        asm volatile("cp.async.commit_group;\n");
        asm volatile("cp.async.wait_group %0;\n" :: "n"(STG - 2));
        __syncthreads();

        if (++read_stage == STG)  read_stage = 0;
        if (++write_stage == STG) write_stage = 0;
    }

    if (LN) {
        const __half* residH = (const __half*)resid;
#pragma unroll
        for (int mi = 0; mi < 4; ++mi) {
            float psum0 = 0.f, psq0 = 0.f, psum1 = 0.f, psq1 = 0.f;
            size_t r0 = mbase + wm * 64 + mi * 16 + (lane >> 2);
            size_t r1 = r0 + 8;
#pragma unroll
            for (int ni = 0; ni < NI; ++ni) {
                int col = wn * WNT + ni * 8 + (lane & 3) * 2;
                float b0 = s_bias[col], b1 = s_bias[col + 1];
                float2 x0, x1;
                if (MODE == 3) {
                    x0 = __half22float2(*(const __half2*)(residH + r0 * 256 + col));
                    x1 = __half22float2(*(const __half2*)(residH + r1 * 256 + col));
                } else {
                    x0 = *(const float2*)(resid + r0 * 256 + col);
                    x1 = *(const float2*)(resid + r1 * 256 + col);
                }
                float v0 = acc[mi][ni][0] + b0 + x0.x;
                float v1 = acc[mi][ni][1] + b1 + x0.y;
                float v2 = acc[mi][ni][2] + b0 + x1.x;
                float v3 = acc[mi][ni][3] + b1 + x1.y;
                acc[mi][ni][0] = v0; acc[mi][ni][1] = v1;
                acc[mi][ni][2] = v2; acc[mi][ni][3] = v3;
                psum0 += v0 + v1; psq0 += v0 * v0 + v1 * v1;
                psum1 += v2 + v3; psq1 += v2 * v2 + v3 * v3;
            }
#pragma unroll
            for (int o = 1; o <= 2; o <<= 1) {
                psum0 += __shfl_xor_sync(0xffffffffu, psum0, o);
                psq0  += __shfl_xor_sync(0xffffffffu, psq0,  o);
                psum1 += __shfl_xor_sync(0xffffffffu, psum1, o);
                psq1  += __shfl_xor_sync(0xffffffffu, psq1,  o);
            }
            if ((lane & 3) == 0) {
                int rl = wm * 64 + mi * 16 + (lane >> 2);
                s_red[rl][wn * 2] = psum0;     s_red[rl][wn * 2 + 1] = psq0;
                s_red[rl + 8][wn * 2] = psum1; s_red[rl + 8][wn * 2 + 1] = psq1;
            }
        }
        s_g[tid] = gam[tid];
        s_b[tid] = bet[tid];
        __syncthreads();

        float mstat[4][2][2];
#pragma unroll
        for (int mi = 0; mi < 4; ++mi) {
#pragma unroll
            for (int hh = 0; hh < 2; ++hh) {
                int rl = wm * 64 + mi * 16 + (lane >> 2) + hh * 8;
                float su = s_red[rl][0] + s_red[rl][2] + s_red[rl][4] + s_red[rl][6];
                float sq = s_red[rl][1] + s_red[rl][3] + s_red[rl][5] + s_red[rl][7];
                float m = su * (1.0f / 256);
                mstat[mi][hh][0] = m;
                mstat[mi][hh][1] = rsqrtf(sq * (1.0f / 256) - m * m + 1e-5f);
            }
        }

        float* C = (float*)Cv;
#pragma unroll
        for (int mi = 0; mi < 4; ++mi) {
            size_t r0 = mbase + wm * 64 + mi * 16 + (lane >> 2);
            size_t r1 = r0 + 8;
            float m0 = mstat[mi][0][0], s0 = mstat[mi][0][1];
            float m1 = mstat[mi][1][0], s1 = mstat[mi][1][1];
#pragma unroll
            for (int ni = 0; ni < NI; ++ni) {
                int col = wn * WNT + ni * 8 + (lane & 3) * 2;
                float g0 = s_g[col], g1v = s_g[col + 1];
                float be0 = s_b[col], be1 = s_b[col + 1];
                float o0 = (acc[mi][ni][0] - m0) * s0 * g0  + be0;
                float o1 = (acc[mi][ni][1] - m0) * s0 * g1v + be1;
                float o2 = (acc[mi][ni][2] - m1) * s1 * g0  + be0;
                float o3 = (acc[mi][ni][3] - m1) * s1 * g1v + be1;
                if (MODE == 2) {
                    *(__half2*)(out16 + r0 * 256 + col) = __floats2half2_rn(o0, o1);
                    *(__half2*)(out16 + r1 * 256 + col) = __floats2half2_rn(o2, o3);
                } else {
                    *(float2*)(C + r0 * 256 + col) = make_float2(o0, o1);
                    *(float2*)(C + r1 * 256 + col) = make_float2(o2, o3);
                }
            }
        }
        return;
    }

#pragma unroll
    for (int mi = 0; mi < 4; ++mi) {
#pragma unroll
        for (int ni = 0; ni < NI; ++ni) {
            int col = nbase + wn * WNT + ni * 8 + (lane & 3) * 2;
            if (col >= N) continue;
            size_t r0 = mbase + wm * 64 + mi * 16 + (lane >> 2);
            size_t r1 = r0 + 8;
            float b0 = s_bias[col - nbase];
            float b1 = s_bias[col - nbase + 1];
            float v0 = acc[mi][ni][0] + b0;
            float v1 = acc[mi][ni][1] + b1;
            float v2 = acc[mi][ni][2] + b0;
            float v3 = acc[mi][ni][3] + b1;
            if (relu) {
                v0 = fmaxf(v0, 0.f); v1 = fmaxf(v1, 0.f);
                v2 = fmaxf(v2, 0.f); v3 = fmaxf(v3, 0.f);
            }
            if (MODE == 1) {
                __half* C = (__half*)Cv;
                *(__half2*)(C + r0 * (size_t)N + col) = __floats2half2_rn(v0, v1);
                *(__half2*)(C + r1 * (size_t)N + col) = __floats2half2_rn(v2, v3);
            } else {
                float* C = (float*)Cv;
                C[r0 * (size_t)N + col]     = v0;
                C[r0 * (size_t)N + col + 1] = v1;
                C[r1 * (size_t)N + col]     = v2;
                C[r1 * (size_t)N + col + 1] = v3;
            }
        }
    }
}

constexpr int SMEM_128_3 = 3 * (BM * 64 + 128 * 64);  // 49152
constexpr int SMEM_256_4 = 4 * (BM * 64 + 256 * 64);  // 98304

// ---------------------------------------------------------------------------
// prep kernels
// ---------------------------------------------------------------------------
__global__ void f2h_kernel(const float* __restrict__ in, __half* __restrict__ out,
                           long n)
{
    long i = ((long)blockIdx.x * blockDim.x + threadIdx.x) * 4;
    if (i < n) {
        float4 v = *(const float4*)(in + i);
        *(__half2*)(out + i)     = __floats2half2_rn(v.x, v.y);
        *(__half2*)(out + i + 2) = __floats2half2_rn(v.z, v.w);
    }
}

__global__ void transpose_h_kernel(const float* __restrict__ in,
                                   __half* __restrict__ out, int K, int N)
{
    __shared__ float t[32][33];
    int k0 = blockIdx.y * 32, n0 = blockIdx.x * 32;
    int x = threadIdx.x, y = threadIdx.y;
#pragma unroll
    for (int i = y; i < 32; i += 8)
        t[i][x] = in[(size_t)(k0 + i) * N + n0 + x];
    __syncthreads();
#pragma unroll
    for (int i = y; i < 32; i += 8)
        out[(size_t)(n0 + i) * K + k0 + x] = __float2half(t[x][i]);
}

__global__ void concat_t_kernel(const float* __restrict__ W_off,
                                const float* __restrict__ b_off,
                                const float* __restrict__ W_aw,
                                const float* __restrict__ b_aw)
{
    int i = blockIdx.x * blockDim.x + threadIdx.x;
    if (i < 128 * CDIM) {
        int n = i / CDIM, k = i % CDIM;
        float v = 0.f;
        if (n < 64)       v = W_off[k * 64 + n];
        else if (n < 96)  v = W_aw[k * 32 + (n - 64)];
        g_WcatT[i] = __float2half(v);
    }
    if (i < 128)
        g_bcat[i] = (i < 64) ? b_off[i] : (i < 96 ? b_aw[i - 64] : 0.f);
}

// ---------------------------------------------------------------------------
// Bilinear sampling: 8 tokens/block, each thread handles 2 tokens (ILP x2).
// ---------------------------------------------------------------------------
__global__ __launch_bounds__(256) void sample_kernel(
    const float* __restrict__ refp, __half* __restrict__ attn, long tokbase)
{
    __shared__ float s_oa[8][NOFFAW];
    __shared__ float2 s_ref[8];

    const int tid = threadIdx.x;
    const int lt  = tid >> 6;
    const int t64 = tid & 63;
    const int h   = t64 >> 3;
    const int l8  = t64 & 7;
    const long tok0 = tokbase + (long)blockIdx.x * 8;

    if (tid < 192) {
        int ltt = tid / 24, e = (tid % 24) * 4;
        *(float4*)&s_oa[ltt][e] =
            *(const float4*)(g_offaw + (tok0 + ltt) * NOFFAW + e);
    } else if (tid < 200) {
        int j = tid - 192;
        s_ref[j] = ((const float2*)refp)[tok0 + j];
    }
    __syncthreads();

    float4 accT[2];
    const float* oaT[2];
    float awwT[2][4];
    const __half* vbT[2];

#pragma unroll
    for (int u = 0; u < 2; ++u) {
        const int sl = lt + u * 4;
        const long token = tok0 + sl;
        const int b = (int)(token / LQ);
        oaT[u] = s_oa[sl];
        const float* oa = oaT[u];
        float l0 = oa[64 + h * 4 + 0], l1 = oa[64 + h * 4 + 1];
        float l2 = oa[64 + h * 4 + 2], l3 = oa[64 + h * 4 + 3];
        float mx = fmaxf(fmaxf(l0, l1), fmaxf(l2, l3));
        float e0 = __expf(l0 - mx), e1 = __expf(l1 - mx);
        float e2 = __expf(l2 - mx), e3 = __expf(l3 - mx);
        float inv = 1.f / (e0 + e1 + e2 + e3);
        awwT[u][0] = e0 * inv; awwT[u][1] = e1 * inv;
        awwT[u][2] = e2 * inv; awwT[u][3] = e3 * inv;
        vbT[u] = g_value_h + ((size_t)b * LQ) * CDIM + h * HD + l8 * 4;
        accT[u] = make_float4(0.f, 0.f, 0.f, 0.f);
    }

#pragma unroll
    for (int p = 0; p < NPT; ++p) {
        float wgt[2][4];
        int xsv[2][4], ysv[2][4];
#pragma unroll
        for (int u = 0; u < 2; ++u) {
            const int sl = lt + u * 4;
            float rx = s_ref[sl].x, ry = s_ref[sl].y;
            float x = rx * WIMG + oaT[u][(h * NPT + p) * 2 + 0] - 0.5f;
            float y = ry * HIMG + oaT[u][(h * NPT + p) * 2 + 1] - 0.5f;
            float x0f = floorf(x), y0f = floorf(y);
            float fx = x - x0f, fy = y - y0f;
            int x0 = (int)x0f, y0 = (int)y0f;
            float a = awwT[u][p];
            wgt[u][0] = a * (1.f - fx) * (1.f - fy);
            wgt[u][1] = a * fx * (1.f - fy);
            wgt[u][2] = a * (1.f - fx) * fy;
            wgt[u][3] = a * fx * fy;
            xsv[u][0] = x0; xsv[u][1] = x0 + 1; xsv[u][2] = x0;     xsv[u][3] = x0 + 1;
            ysv[u][0] = y0; ysv[u][1] = y0;     ysv[u][2] = y0 + 1; ysv[u][3] = y0 + 1;
        }
#pragma unroll
        for (int c = 0; c < 4; ++c) {
#pragma unroll
            for (int u = 0; u < 2; ++u) {
                int xi = xsv[u][c], yi = ysv[u][c];
                float w = wgt[u][c];
                if (xi >= 0 && xi < WIMG && yi >= 0 && yi < HIMG && w != 0.f) {
                    const __half2* vp =
                        (const __half2*)(vbT[u] + (size_t)(yi * WIMG + xi) * CDIM);
                    float2 u0 = __half22float2(vp[0]);
                    float2 u1 = __half22float2(vp[1]);
                    accT[u].x += u0.x * w; accT[u].y += u0.y * w;
                    accT[u].z += u1.x * w; accT[u].w += u1.y * w;
                }
            }
        }
    }

#pragma unroll
    for (int u = 0; u < 2; ++u) {
        const long token = tok0 + lt + u * 4;
        __half* dst = attn + (size_t)token * CDIM + h * HD + l8 * 4;
        *(__half2*)(dst)     = __floats2half2_rn(accT[u].x, accT[u].y);
        *(__half2*)(dst + 2) = __floats2half2_rn(accT[u].z, accT[u].w);
    }
}

// ---------------------------------------------------------------------------
// Launch: two-stream prep overlap + batch-split value GEMM + pipelined back half
// ---------------------------------------------------------------------------
extern "C" void kernel_launch(void* const* d_in, const int* in_sizes, int n_in,
                              void* d_out, int out_size)
{
    const float* query = (const float*)d_in[0];
    const float* src   = (const float*)d_in[1];
    const float* refp  = (const float*)d_in[2];
    const float* W_off = (const float*)d_in[5];
    const float* b_off = (const float*)d_in[6];
    const float* W_aw  = (const float*)d_in[7];
    const float* b_aw  = (const float*)d_in[8];
    const float* W_val = (const float*)d_in[9];
    const float* b_val = (const float*)d_in[10];
    const float* W_out = (const float*)d_in[11];
    const float* b_out = (const float*)d_in[12];
    const float* g1    = (const float*)d_in[13];
    const float* be1   = (const float*)d_in[14];
    const float* W1    = (const float*)d_in[15];
    const float* b1    = (const float*)d_in[16];
    const float* W2    = (const float*)d_in[17];
    const float* b2    = (const float*)d_in[18];
    const float* g2    = (const float*)d_in[19];
    const float* be2   = (const float*)d_in[20];
    float* out = (float*)d_out;

    __half *p_src_h, *p_query_h, *p_value_h, *p_attn_h, *p_q2_h, *p_ffn_h;
    __half *p_WvalT, *p_WoutT, *p_W1T, *p_W2T, *p_WcatT;
    float *p_offaw, *p_bcat;
    cudaGetSymbolAddress((void**)&p_src_h,   g_src_h);
    cudaGetSymbolAddress((void**)&p_query_h, g_query_h);
    cudaGetSymbolAddress((void**)&p_value_h, g_value_h);
    cudaGetSymbolAddress((void**)&p_attn_h,  g_attn_h);
    cudaGetSymbolAddress((void**)&p_q2_h,    g_q2_h);
    cudaGetSymbolAddress((void**)&p_ffn_h,   g_ffn_h);
    cudaGetSymbolAddress((void**)&p_offaw,   g_offaw);
    cudaGetSymbolAddress((void**)&p_WvalT,   g_WvalT);
    cudaGetSymbolAddress((void**)&p_WoutT,   g_WoutT);
    cudaGetSymbolAddress((void**)&p_W1T,     g_W1T);
    cudaGetSymbolAddress((void**)&p_W2T,     g_W2T);
    cudaGetSymbolAddress((void**)&p_WcatT,   g_WcatT);
    cudaGetSymbolAddress((void**)&p_bcat,    g_bcat);

    static cudaStream_t s1 = nullptr;
    static cudaEvent_t evFork = nullptr, evB = nullptr, evC = nullptr,
                       evSrc = nullptr, evVal0 = nullptr, evD = nullptr;
    static bool attr_done = false;
    if (!s1) {
        cudaStreamCreateWithFlags(&s1, cudaStreamNonBlocking);
        cudaEventCreateWithFlags(&evFork, cudaEventDisableTiming);
        cudaEventCreateWithFlags(&evB,    cudaEventDisableTiming);
        cudaEventCreateWithFlags(&evC,    cudaEventDisableTiming);
        cudaEventCreateWithFlags(&evSrc,  cudaEventDisableTiming);
        cudaEventCreateWithFlags(&evVal0, cudaEventDisableTiming);
        cudaEventCreateWithFlags(&evD,    cudaEventDisableTiming);
    }
    if (!attr_done) {
        cudaFuncSetAttribute(gemm_h_kernel<128, 0, 3>,
                             cudaFuncAttributeMaxDynamicSharedMemorySize, SMEM_128_3);
        cudaFuncSetAttribute(gemm_h_kernel<128, 1, 3>,
                             cudaFuncAttributeMaxDynamicSharedMemorySize, SMEM_128_3);
        cudaFuncSetAttribute(gemm_h_kernel<256, 2, 4>,
                             cudaFuncAttributeMaxDynamicSharedMemorySize, SMEM_256_4);
        cudaFuncSetAttribute(gemm_h_kernel<256, 3, 4>,
                             cudaFuncAttributeMaxDynamicSharedMemorySize, SMEM_256_4);
        attr_done = true;
    }

    dim3 tb(32, 8);
    const long NELT = (long)MTOK * CDIM;
    const int F2H_GRID = (int)((NELT / 4 + 255) / 256);

    // value GEMM split: P0 rows [0, 50048) on A (covers chunk0, batches 0-4);
    // P1 rows [50048, 80000) on s1.
    const int VAL_MB0 = 391, VAL_MB1 = 234;
    const int VAL_ROW1 = VAL_MB0 * BM;     // 50048

    // ---- fork ----
    cudaEventRecord(evFork, 0);
    cudaStreamWaitEvent(s1, evFork, 0);

    // stream B (s1): query-side chain + weight preps
    f2h_kernel<<<F2H_GRID, 256, 0, s1>>>(query, p_query_h, NELT);
    concat_t_kernel<<<(128 * CDIM + 255) / 256, 256, 0, s1>>>(W_off, b_off, W_aw, b_aw);
    gemm_h_kernel<128, 0, 3><<<dim3(1, MTOK / BM), 256, SMEM_128_3, s1>>>(
        p_query_h, p_WcatT, p_bcat, p_offaw, NOFFAW, CDIM, 0,
        nullptr, nullptr, nullptr, nullptr, 0);
    cudaEventRecord(evB, s1);
    transpose_h_kernel<<<dim3(CDIM / 32, CDIM / 32), tb, 0, s1>>>(W_out, p_WoutT, CDIM, CDIM);
    transpose_h_kernel<<<dim3(DFF / 32,  CDIM / 32), tb, 0, s1>>>(W1, p_W1T, CDIM, DFF);
    transpose_h_kernel<<<dim3(CDIM / 32, DFF / 32),  tb, 0, s1>>>(W2, p_W2T, DFF, CDIM);
    cudaEventRecord(evC, s1);

    // stream A (default): src-side chain -> value P0
    f2h_kernel<<<F2H_GRID, 256>>>(src, p_src_h, NELT);
    transpose_h_kernel<<<dim3(CDIM / 32, CDIM / 32), tb>>>(W_val, p_WvalT, CDIM, CDIM);
    cudaEventRecord(evSrc, 0);
    gemm_h_kernel<128, 1, 3><<<dim3(2, VAL_MB0), 256, SMEM_128_3>>>(
        p_src_h, p_WvalT, b_val, p_value_h, CDIM, CDIM, 0,
        nullptr, nullptr, nullptr, nullptr, 0);
    cudaEventRecord(evVal0, 0);

    // value P1 on s1 (after src_h/WvalT ready)
    cudaStreamWaitEvent(s1, evSrc, 0);
    gemm_h_kernel<128, 1, 3><<<dim3(2, VAL_MB1), 256, SMEM_128_3, s1>>>(
        p_src_h, p_WvalT, b_val, p_value_h, CDIM, CDIM, 0,
        nullptr, nullptr, nullptr, nullptr, VAL_ROW1);

    // ---- back half, two row-chunks pipelined across the two streams ----
    const int MB0 = 313, MB1 = 312;            // tokens [0,40064) / [40064,80000)
    const int MBc[2]  = {MB0, MB1};
    const int ROWc[2] = {0, MB0 * BM};
    cudaStream_t st[2] = {(cudaStream_t)0, s1};

    // chunk0 (A): sampler needs only offaw (evB); value P0 sequenced on A.
    // The weight transposes (evC) are needed only by the W_out GEMM, so that
    // wait happens after the sampler launch (inside the loop, c==0).
    cudaStreamWaitEvent(0, evB, 0);
    cudaStreamWaitEvent(s1, evVal0, 0);

    for (int c = 0; c < 2; ++c) {
        cudaStream_t s = st[c];
        const int mb = MBc[c], row0 = ROWc[c];
        sample_kernel<<<mb * BM / 8, 256, 0, s>>>(refp, p_attn_h, row0);
        if (c == 0) cudaStreamWaitEvent(0, evC, 0);   // weights needed from here on
        // W_out + residual(query f32) + LN1 -> q2_h (fp16 only)
        gemm_h_kernel<256, 2, 4><<<dim3(1, mb), 256, SMEM_256_4, s>>>(
            p_attn_h, p_WoutT, b_out, nullptr, CDIM, CDIM, 0,
            query, g1, be1, p_q2_h, row0);
        // FFN1 (relu, fp16 out)
        gemm_h_kernel<128, 1, 3><<<dim3(DFF / 128, mb), 256, SMEM_128_3, s>>>(
            p_q2_h, p_W1T, b1, p_ffn_h, DFF, CDIM, 1,
            nullptr, nullptr, nullptr, nullptr, row0);
        // FFN2 + residual(q2_h fp16) + LN2 -> final f32 out
        gemm_h_kernel<256, 3, 4><<<dim3(1, mb), 256, SMEM_256_4, s>>>(
            p_ffn_h, p_W2T, b2, out, CDIM, DFF, 0,
            (const float*)p_q2_h, g2, be2, nullptr, row0);
    }

    // join s1 back to the origin stream (capture requires it)
    cudaEventRecord(evD, s1);
    cudaStreamWaitEvent(0, evD, 0);
}

// round 15
// speedup vs baseline: 1.0585x; 1.0017x over previous
#include <cuda_runtime.h>
#include <cuda_fp16.h>
#include <cstdint>

#define DEV_INLINE __device__ __forceinline__

constexpr int BB   = 8;
constexpr int LQ   = 10000;
constexpr int CDIM = 256;
constexpr int NHD  = 8;
constexpr int NPT  = 4;
constexpr int DFF  = 1024;
constexpr int HIMG = 100;
constexpr int WIMG = 100;
constexpr int HD   = 32;
constexpr int MTOK = BB * LQ;  // 80000
constexpr int NOFFAW = 96;

// fp16 activations
__device__ __half g_value_h[MTOK * CDIM];
__device__ __half g_attn_h [MTOK * CDIM];
__device__ __half g_q2_h   [MTOK * CDIM];
__device__ __half g_ffn_h  [MTOK * DFF];
// fp32 buffers
__device__ float g_offaw[MTOK * NOFFAW];
// fp16 transposed weights [N][K]
__device__ __half g_WvalT[CDIM * CDIM];
__device__ __half g_WoutT[CDIM * CDIM];
__device__ __half g_W1T  [DFF * CDIM];
__device__ __half g_W2T  [CDIM * DFF];
__device__ __half g_WcatT[128 * CDIM];
__device__ float  g_bcat [128];

// ---------------------------------------------------------------------------
// MMA / ldmatrix helpers
// ---------------------------------------------------------------------------
DEV_INLINE void mma_f16(float* d, const uint32_t* a, const uint32_t* b) {
    asm volatile(
        "mma.sync.aligned.m16n8k16.row.col.f32.f16.f16.f32 "
        "{%0,%1,%2,%3}, {%4,%5,%6,%7}, {%8,%9}, {%0,%1,%2,%3};\n"
        : "+f"(d[0]), "+f"(d[1]), "+f"(d[2]), "+f"(d[3])
        : "r"(a[0]), "r"(a[1]), "r"(a[2]), "r"(a[3]), "r"(b[0]), "r"(b[1]));
}

DEV_INLINE void ldsm_x4(uint32_t* r, uint32_t addr) {
    asm volatile("ldmatrix.sync.aligned.m8n8.x4.shared.b16 {%0,%1,%2,%3}, [%4];"
                 : "=r"(r[0]), "=r"(r[1]), "=r"(r[2]), "=r"(r[3]) : "r"(addr));
}

DEV_INLINE void cp_async16(uint32_t dst, const void* src) {
    asm volatile("cp.async.cg.shared.global [%0], [%1], 16;\n" :: "r"(dst), "l"(src));
}

DEV_INLINE uint32_t h2u(__half2 h) { return *(uint32_t*)&h; }

// ---------------------------------------------------------------------------
// fp16 tensor-core GEMM: acc = A[M,K] @ BT[N,K]^T  (rows offset by mrow0)
// MODE 0: f32 out      MODE 1: fp16 out
// MODE 2: LN, residual f32, writes fp16 out16 only     (W_out + LN1 -> q2_h)
// MODE 3: LN, residual fp16, writes f32 Cv only        (FFN2 + LN2)
// F32A 1: A operand is fp32 in gmem; converted to fp16 during smem staging
//         (register-prefetch LDG + STS instead of cp.async for A).
// ---------------------------------------------------------------------------
constexpr int BM = 128, BK = 32;

template<int BN_, int MODE, int STG, int F32A>
__global__ __launch_bounds__(256, (BN_ <= 128) ? 2 : 1) void gemm_h_kernel(
    const __half* __restrict__ A, const __half* __restrict__ BT,
    const float* __restrict__ bias, void* __restrict__ Cv,
    int N, int K, int relu,
    const float* __restrict__ resid, const float* __restrict__ gam,
    const float* __restrict__ bet, __half* __restrict__ out16,
    int mrow0)
{
    constexpr int WNT = BN_ / 4;
    constexpr int NI  = WNT / 8;
    constexpr int A_BYTES = BM * 64;
    constexpr int B_BYTES = BN_ * 64;
    constexpr int STAGE_BYTES = A_BYTES + B_BYTES;
    constexpr bool LN = (MODE >= 2);

    extern __shared__ char dsm[];
    uint32_t sm0 = (uint32_t)__cvta_generic_to_shared(dsm);

    __shared__ float s_bias[BN_];
    __shared__ float s_red[LN ? 128 : 1][8];
    __shared__ float s_g[LN ? 256 : 1], s_b[LN ? 256 : 1];

    const int tid  = threadIdx.x;
    const int lane = tid & 31;
    const int wid  = tid >> 5;
    const int wm   = wid >> 2;
    const int wn   = wid & 3;
    const size_t mbase = (size_t)mrow0 + (size_t)blockIdx.y * BM;
    const int    nbase = blockIdx.x * BN_;

    const int g  = lane >> 3;
    const int rr = lane & 7;

    const int rowA = wm * 64 + rr + (g & 1) * 8;
    const uint32_t swA = (uint32_t)((rowA >> 1) & 3);
    const uint32_t aoff[2] = { (((0u + (g >> 1)) ^ swA) << 4),
                               (((2u + (g >> 1)) ^ swA) << 4) };
    const uint32_t aBase = (uint32_t)rowA * 64u;

    const int rowB = wn * WNT + rr + (g >> 1) * 8;
    const uint32_t swB = (uint32_t)((rowB >> 1) & 3);
    const uint32_t boff[2] = { (((0u + (g & 1)) ^ swB) << 4),
                               (((2u + (g & 1)) ^ swB) << 4) };
    const uint32_t bBase = (uint32_t)rowB * 64u;

    const int arow = tid >> 1;
    const int ac   = tid & 1;
    const __half* Ab  = A + mbase * (size_t)K;                 // F32A == 0
    const float*  Af  = (const float*)A + (mbase + arow) * (size_t)K + ac * 16;

    for (int c = tid; c < BN_; c += 256) s_bias[c] = bias[nbase + c];

    float acc[4][NI][4];
#pragma unroll
    for (int mi = 0; mi < 4; ++mi)
#pragma unroll
        for (int ni = 0; ni < NI; ++ni)
#pragma unroll
            for (int j = 0; j < 4; ++j) acc[mi][ni][j] = 0.f;

    float4 pA[4];

    auto lda = [&](int k0) {
        const float* p = Af + k0;
        pA[0] = *(const float4*)(p + 0);
        pA[1] = *(const float4*)(p + 4);
        pA[2] = *(const float4*)(p + 8);
        pA[3] = *(const float4*)(p + 12);
    };
    auto stsA = [&](int stage) {
#pragma unroll
        for (int i = 0; i < 2; ++i) {
            int c = ac * 2 + i;
            uint32_t off = (uint32_t)stage * STAGE_BYTES + (uint32_t)arow * 64u
                         + (((uint32_t)c ^ (((uint32_t)arow >> 1) & 3u)) << 4);
            uint4 v;
            v.x = h2u(__floats2half2_rn(pA[2 * i].x, pA[2 * i].y));
            v.y = h2u(__floats2half2_rn(pA[2 * i].z, pA[2 * i].w));
            v.z = h2u(__floats2half2_rn(pA[2 * i + 1].x, pA[2 * i + 1].y));
            v.w = h2u(__floats2half2_rn(pA[2 * i + 1].z, pA[2 * i + 1].w));
            *(uint4*)(dsm + off) = v;
        }
    };
    auto loadA_cp = [&](int stage, int k0) {
        uint32_t sA = sm0 + stage * STAGE_BYTES;
#pragma unroll
        for (int i = 0; i < 2; ++i) {
            int c = ac * 2 + i;
            cp_async16(sA + arow * 64 + ((c ^ ((arow >> 1) & 3)) << 4),
                       Ab + (size_t)arow * K + k0 + c * 8);
        }
    };
    auto loadB = [&](int stage, int k0) {
        uint32_t sB = sm0 + stage * STAGE_BYTES + A_BYTES;
#pragma unroll
        for (int it = 0; it < BN_ / 64; ++it) {
            int idx = tid + it * 256;
            int row = idx >> 2, c = idx & 3;
            cp_async16(sB + row * 64 + ((c ^ ((row >> 1) & 3)) << 4),
                       BT + (size_t)(nbase + row) * K + k0 + c * 8);
        }
    };

    const int ntiles = K / BK;

#pragma unroll
    for (int s = 0; s < STG - 1; ++s) {
        if (s < ntiles) {
            if (F32A) { lda(s * BK); stsA(s); }
            else      loadA_cp(s, s * BK);
            loadB(s, s * BK);
        }
        asm volatile("cp.async.commit_group;\n");
    }
    asm volatile("cp.async.wait_group %0;\n" :: "n"(STG - 2));
    __syncthreads();

    int read_stage = 0, write_stage = STG - 1;

    for (int i = 0; i < ntiles; ++i) {
        const int j = i + STG - 1;
        if (F32A && j < ntiles) lda(j * BK);   // LDG overlaps the MMA block

        uint32_t sA = sm0 + read_stage * STAGE_BYTES;
        uint32_t sB = sA + A_BYTES;

#pragma unroll
        for (int ks = 0; ks < 2; ++ks) {
            uint32_t afr[4][4], bfr[NI / 2][4];
#pragma unroll
            for (int mi = 0; mi < 4; ++mi)
                ldsm_x4(afr[mi], sA + aBase + mi * 1024 + aoff[ks]);
#pragma unroll
            for (int p = 0; p < NI / 2; ++p)
                ldsm_x4(bfr[p], sB + bBase + p * 1024 + boff[ks]);
#pragma unroll
            for (int mi = 0; mi < 4; ++mi)
#pragma unroll
                for (int ni = 0; ni < NI; ++ni)
                    mma_f16(acc[mi][ni], afr[mi], &bfr[ni >> 1][(ni & 1) * 2]);
        }

        if (j < ntiles) {
            if (F32A) stsA(write_stage);
            else      loadA_cp(write_stage, j * BK);
            loadB(write_stage, j * BK);
        }
        asm volatile("cp.async.commit_group;\n");
        asm volatile("cp.async.wait_group %0;\n" :: "n"(STG - 2));
        __syncthreads();

        if (++read_stage == STG)  read_stage = 0;
        if (++write_stage == STG) write_stage = 0;
    }

    if (LN) {
        const __half* residH = (const __half*)resid;
#pragma unroll
        for (int mi = 0; mi < 4; ++mi) {
            float psum0 = 0.f, psq0 = 0.f, psum1 = 0.f, psq1 = 0.f;
            size_t r0 = mbase + wm * 64 + mi * 16 + (lane >> 2);
            size_t r1 = r0 + 8;
#pragma unroll
            for (int ni = 0; ni < NI; ++ni) {
                int col = wn * WNT + ni * 8 + (lane & 3) * 2;
                float b0 = s_bias[col], b1 = s_bias[col + 1];
                float2 x0, x1;
                if (MODE == 3) {
                    x0 = __half22float2(*(const __half2*)(residH + r0 * 256 + col));
                    x1 = __half22float2(*(const __half2*)(residH + r1 * 256 + col));
                } else {
                    x0 = *(const float2*)(resid + r0 * 256 + col);
                    x1 = *(const float2*)(resid + r1 * 256 + col);
                }
                float v0 = acc[mi][ni][0] + b0 + x0.x;
                float v1 = acc[mi][ni][1] + b1 + x0.y;
                float v2 = acc[mi][ni][2] + b0 + x1.x;
                float v3 = acc[mi][ni][3] + b1 + x1.y;
                acc[mi][ni][0] = v0; acc[mi][ni][1] = v1;
                acc[mi][ni][2] = v2; acc[mi][ni][3] = v3;
                psum0 += v0 + v1; psq0 += v0 * v0 + v1 * v1;
                psum1 += v2 + v3; psq1 += v2 * v2 + v3 * v3;
            }
#pragma unroll
            for (int o = 1; o <= 2; o <<= 1) {
                psum0 += __shfl_xor_sync(0xffffffffu, psum0, o);
                psq0  += __shfl_xor_sync(0xffffffffu, psq0,  o);
                psum1 += __shfl_xor_sync(0xffffffffu, psum1, o);
                psq1  += __shfl_xor_sync(0xffffffffu, psq1,  o);
            }
            if ((lane & 3) == 0) {
                int rl = wm * 64 + mi * 16 + (lane >> 2);
                s_red[rl][wn * 2] = psum0;     s_red[rl][wn * 2 + 1] = psq0;
                s_red[rl + 8][wn * 2] = psum1; s_red[rl + 8][wn * 2 + 1] = psq1;
            }
        }
        s_g[tid] = gam[tid];
        s_b[tid] = bet[tid];
        __syncthreads();

        float mstat[4][2][2];
#pragma unroll
        for (int mi = 0; mi < 4; ++mi) {
#pragma unroll
            for (int hh = 0; hh < 2; ++hh) {
                int rl = wm * 64 + mi * 16 + (lane >> 2) + hh * 8;
                float su = s_red[rl][0] + s_red[rl][2] + s_red[rl][4] + s_red[rl][6];
                float sq = s_red[rl][1] + s_red[rl][3] + s_red[rl][5] + s_red[rl][7];
                float m = su * (1.0f / 256);
                mstat[mi][hh][0] = m;
                mstat[mi][hh][1] = rsqrtf(sq * (1.0f / 256) - m * m + 1e-5f);
            }
        }

        float* C = (float*)Cv;
#pragma unroll
        for (int mi = 0; mi < 4; ++mi) {
            size_t r0 = mbase + wm * 64 + mi * 16 + (lane >> 2);
            size_t r1 = r0 + 8;
            float m0 = mstat[mi][0][0], s0 = mstat[mi][0][1];
            float m1 = mstat[mi][1][0], s1 = mstat[mi][1][1];
#pragma unroll
            for (int ni = 0; ni < NI; ++ni) {
                int col = wn * WNT + ni * 8 + (lane & 3) * 2;
                float g0 = s_g[col], g1v = s_g[col + 1];
                float be0 = s_b[col], be1 = s_b[col + 1];
                float o0 = (acc[mi][ni][0] - m0) * s0 * g0  + be0;
                float o1 = (acc[mi][ni][1] - m0) * s0 * g1v + be1;
                float o2 = (acc[mi][ni][2] - m1) * s1 * g0  + be0;
                float o3 = (acc[mi][ni][3] - m1) * s1 * g1v + be1;
                if (MODE == 2) {
                    *(__half2*)(out16 + r0 * 256 + col) = __floats2half2_rn(o0, o1);
                    *(__half2*)(out16 + r1 * 256 + col) = __floats2half2_rn(o2, o3);
                } else {
                    *(float2*)(C + r0 * 256 + col) = make_float2(o0, o1);
                    *(float2*)(C + r1 * 256 + col) = make_float2(o2, o3);
                }
            }
        }
        return;
    }

#pragma unroll
    for (int mi = 0; mi < 4; ++mi) {
#pragma unroll
        for (int ni = 0; ni < NI; ++ni) {
            int col = nbase + wn * WNT + ni * 8 + (lane & 3) * 2;
            if (col >= N) continue;
            size_t r0 = mbase + wm * 64 + mi * 16 + (lane >> 2);
            size_t r1 = r0 + 8;
            float b0 = s_bias[col - nbase];
            float b1 = s_bias[col - nbase + 1];
            float v0 = acc[mi][ni][0] + b0;
            float v1 = acc[mi][ni][1] + b1;
            float v2 = acc[mi][ni][2] + b0;
            float v3 = acc[mi][ni][3] + b1;
            if (relu) {
                v0 = fmaxf(v0, 0.f); v1 = fmaxf(v1, 0.f);
                v2 = fmaxf(v2, 0.f); v3 = fmaxf(v3, 0.f);
            }
            if (MODE == 1) {
                __half* C = (__half*)Cv;
                *(__half2*)(C + r0 * (size_t)N + col) = __floats2half2_rn(v0, v1);
                *(__half2*)(C + r1 * (size_t)N + col) = __floats2half2_rn(v2, v3);
            } else {
                float* C = (float*)Cv;
                C[r0 * (size_t)N + col]     = v0;
                C[r0 * (size_t)N + col + 1] = v1;
                C[r1 * (size_t)N + col]     = v2;
                C[r1 * (size_t)N + col + 1] = v3;
            }
        }
    }
}

constexpr int SMEM_128_3 = 3 * (BM * 64 + 128 * 64);  // 49152
constexpr int SMEM_256_4 = 4 * (BM * 64 + 256 * 64);  // 98304

// ---------------------------------------------------------------------------
// prep kernels
// ---------------------------------------------------------------------------
__global__ void transpose_h_kernel(const float* __restrict__ in,
                                   __half* __restrict__ out, int K, int N)
{
    __shared__ float t[32][33];
    int k0 = blockIdx.y * 32, n0 = blockIdx.x * 32;
    int x = threadIdx.x, y = threadIdx.y;
#pragma unroll
    for (int i = y; i < 32; i += 8)
        t[i][x] = in[(size_t)(k0 + i) * N + n0 + x];
    __syncthreads();
#pragma unroll
    for (int i = y; i < 32; i += 8)
        out[(size_t)(n0 + i) * K + k0 + x] = __float2half(t[x][i]);
}

__global__ void concat_t_kernel(const float* __restrict__ W_off,
                                const float* __restrict__ b_off,
                                const float* __restrict__ W_aw,
                                const float* __restrict__ b_aw)
{
    int i = blockIdx.x * blockDim.x + threadIdx.x;
    if (i < 128 * CDIM) {
        int n = i / CDIM, k = i % CDIM;
        float v = 0.f;
        if (n < 64)       v = W_off[k * 64 + n];
        else if (n < 96)  v = W_aw[k * 32 + (n - 64)];
        g_WcatT[i] = __float2half(v);
    }
    if (i < 128)
        g_bcat[i] = (i < 64) ? b_off[i] : (i < 96 ? b_aw[i - 64] : 0.f);
}

// ---------------------------------------------------------------------------
// Bilinear sampling: 8 tokens/block, each thread handles 2 tokens (ILP x2).
// ---------------------------------------------------------------------------
__global__ __launch_bounds__(256) void sample_kernel(
    const float* __restrict__ refp, __half* __restrict__ attn, long tokbase)
{
    __shared__ float s_oa[8][NOFFAW];
    __shared__ float2 s_ref[8];

    const int tid = threadIdx.x;
    const int lt  = tid >> 6;
    const int t64 = tid & 63;
    const int h   = t64 >> 3;
    const int l8  = t64 & 7;
    const long tok0 = tokbase + (long)blockIdx.x * 8;

    if (tid < 192) {
        int ltt = tid / 24, e = (tid % 24) * 4;
        *(float4*)&s_oa[ltt][e] =
            *(const float4*)(g_offaw + (tok0 + ltt) * NOFFAW + e);
    } else if (tid < 200) {
        int j = tid - 192;
        s_ref[j] = ((const float2*)refp)[tok0 + j];
    }
    __syncthreads();

    float4 accT[2];
    const float* oaT[2];
    float awwT[2][4];
    const __half* vbT[2];

#pragma unroll
    for (int u = 0; u < 2; ++u) {
        const int sl = lt + u * 4;
        const long token = tok0 + sl;
        const int b = (int)(token / LQ);
        oaT[u] = s_oa[sl];
        const float* oa = oaT[u];
        float l0 = oa[64 + h * 4 + 0], l1 = oa[64 + h * 4 + 1];
        float l2 = oa[64 + h * 4 + 2], l3 = oa[64 + h * 4 + 3];
        float mx = fmaxf(fmaxf(l0, l1), fmaxf(l2, l3));
        float e0 = __expf(l0 - mx), e1 = __expf(l1 - mx);
        float e2 = __expf(l2 - mx), e3 = __expf(l3 - mx);
        float inv = 1.f / (e0 + e1 + e2 + e3);
        awwT[u][0] = e0 * inv; awwT[u][1] = e1 * inv;
        awwT[u][2] = e2 * inv; awwT[u][3] = e3 * inv;
        vbT[u] = g_value_h + ((size_t)b * LQ) * CDIM + h * HD + l8 * 4;
        accT[u] = make_float4(0.f, 0.f, 0.f, 0.f);
    }

#pragma unroll
    for (int p = 0; p < NPT; ++p) {
        float wgt[2][4];
        int xsv[2][4], ysv[2][4];
#pragma unroll
        for (int u = 0; u < 2; ++u) {
            const int sl = lt + u * 4;
            float rx = s_ref[sl].x, ry = s_ref[sl].y;
            float x = rx * WIMG + oaT[u][(h * NPT + p) * 2 + 0] - 0.5f;
            float y = ry * HIMG + oaT[u][(h * NPT + p) * 2 + 1] - 0.5f;
            float x0f = floorf(x), y0f = floorf(y);
            float fx = x - x0f, fy = y - y0f;
            int x0 = (int)x0f, y0 = (int)y0f;
            float a = awwT[u][p];
            wgt[u][0] = a * (1.f - fx) * (1.f - fy);
            wgt[u][1] = a * fx * (1.f - fy);
            wgt[u][2] = a * (1.f - fx) * fy;
            wgt[u][3] = a * fx * fy;
            xsv[u][0] = x0; xsv[u][1] = x0 + 1; xsv[u][2] = x0;     xsv[u][3] = x0 + 1;
            ysv[u][0] = y0; ysv[u][1] = y0;     ysv[u][2] = y0 + 1; ysv[u][3] = y0 + 1;
        }
#pragma unroll
        for (int c = 0; c < 4; ++c) {
#pragma unroll
            for (int u = 0; u < 2; ++u) {
                int xi = xsv[u][c], yi = ysv[u][c];
                float w = wgt[u][c];
                if (xi >= 0 && xi < WIMG && yi >= 0 && yi < HIMG && w != 0.f) {
                    const __half2* vp =
                        (const __half2*)(vbT[u] + (size_t)(yi * WIMG + xi) * CDIM);
                    float2 u0 = __half22float2(vp[0]);
                    float2 u1 = __half22float2(vp[1]);
                    accT[u].x += u0.x * w; accT[u].y += u0.y * w;
                    accT[u].z += u1.x * w; accT[u].w += u1.y * w;
                }
            }
        }
    }

#pragma unroll
    for (int u = 0; u < 2; ++u) {
        const long token = tok0 + lt + u * 4;
        __half* dst = attn + (size_t)token * CDIM + h * HD + l8 * 4;
        *(__half2*)(dst)     = __floats2half2_rn(accT[u].x, accT[u].y);
        *(__half2*)(dst + 2) = __floats2half2_rn(accT[u].z, accT[u].w);
    }
}

// ---------------------------------------------------------------------------
// Launch
// ---------------------------------------------------------------------------
extern "C" void kernel_launch(void* const* d_in, const int* in_sizes, int n_in,
                              void* d_out, int out_size)
{
    const float* query = (const float*)d_in[0];
    const float* src   = (const float*)d_in[1];
    const float* refp  = (const float*)d_in[2];
    const float* W_off = (const float*)d_in[5];
    const float* b_off = (const float*)d_in[6];
    const float* W_aw  = (const float*)d_in[7];
    const float* b_aw  = (const float*)d_in[8];
    const float* W_val = (const float*)d_in[9];
    const float* b_val = (const float*)d_in[10];
    const float* W_out = (const float*)d_in[11];
    const float* b_out = (const float*)d_in[12];
    const float* g1    = (const float*)d_in[13];
    const float* be1   = (const float*)d_in[14];
    const float* W1    = (const float*)d_in[15];
    const float* b1    = (const float*)d_in[16];
    const float* W2    = (const float*)d_in[17];
    const float* b2    = (const float*)d_in[18];
    const float* g2    = (const float*)d_in[19];
    const float* be2   = (const float*)d_in[20];
    float* out = (float*)d_out;

    __half *p_value_h, *p_attn_h, *p_q2_h, *p_ffn_h;
    __half *p_WvalT, *p_WoutT, *p_W1T, *p_W2T, *p_WcatT;
    float *p_offaw, *p_bcat;
    cudaGetSymbolAddress((void**)&p_value_h, g_value_h);
    cudaGetSymbolAddress((void**)&p_attn_h,  g_attn_h);
    cudaGetSymbolAddress((void**)&p_q2_h,    g_q2_h);
    cudaGetSymbolAddress((void**)&p_ffn_h,   g_ffn_h);
    cudaGetSymbolAddress((void**)&p_offaw,   g_offaw);
    cudaGetSymbolAddress((void**)&p_WvalT,   g_WvalT);
    cudaGetSymbolAddress((void**)&p_WoutT,   g_WoutT);
    cudaGetSymbolAddress((void**)&p_W1T,     g_W1T);
    cudaGetSymbolAddress((void**)&p_W2T,     g_W2T);
    cudaGetSymbolAddress((void**)&p_WcatT,   g_WcatT);
    cudaGetSymbolAddress((void**)&p_bcat,    g_bcat);

    static cudaStream_t s1 = nullptr;
    static cudaEvent_t evFork = nullptr, evW = nullptr, evB = nullptr,
                       evC = nullptr, evVal0 = nullptr, evD = nullptr;
    static bool attr_done = false;
    if (!s1) {
        cudaStreamCreateWithFlags(&s1, cudaStreamNonBlocking);
        cudaEventCreateWithFlags(&evFork, cudaEventDisableTiming);
        cudaEventCreateWithFlags(&evW,    cudaEventDisableTiming);
        cudaEventCreateWithFlags(&evB,    cudaEventDisableTiming);
        cudaEventCreateWithFlags(&evC,    cudaEventDisableTiming);
        cudaEventCreateWithFlags(&evVal0, cudaEventDisableTiming);
        cudaEventCreateWithFlags(&evD,    cudaEventDisableTiming);
    }
    if (!attr_done) {
        cudaFuncSetAttribute(gemm_h_kernel<128, 0, 3, 1>,
                             cudaFuncAttributeMaxDynamicSharedMemorySize, SMEM_128_3);
        cudaFuncSetAttribute(gemm_h_kernel<128, 1, 3, 1>,
                             cudaFuncAttributeMaxDynamicSharedMemorySize, SMEM_128_3);
        cudaFuncSetAttribute(gemm_h_kernel<128, 1, 3, 0>,
                             cudaFuncAttributeMaxDynamicSharedMemorySize, SMEM_128_3);
        cudaFuncSetAttribute(gemm_h_kernel<256, 2, 4, 0>,
                             cudaFuncAttributeMaxDynamicSharedMemorySize, SMEM_256_4);
        cudaFuncSetAttribute(gemm_h_kernel<256, 3, 4, 0>,
                             cudaFuncAttributeMaxDynamicSharedMemorySize, SMEM_256_4);
        attr_done = true;
    }

    dim3 tb(32, 8);

    // value GEMM split: P0 rows [0, 50048) on A (covers chunk0, batches 0-4);
    // P1 rows [50048, 80000) on s1.
    const int VAL_MB0 = 391, VAL_MB1 = 234;
    const int VAL_ROW1 = VAL_MB0 * BM;     // 50048

    // ---- fork ----
    cudaEventRecord(evFork, 0);
    cudaStreamWaitEvent(s1, evFork, 0);

    // stream A (default): WvalT -> value P0 (reads src f32 directly)
    transpose_h_kernel<<<dim3(CDIM / 32, CDIM / 32), tb>>>(W_val, p_WvalT, CDIM, CDIM);
    cudaEventRecord(evW, 0);
    gemm_h_kernel<128, 1, 3, 1><<<dim3(2, VAL_MB0), 256, SMEM_128_3>>>(
        (const __half*)src, p_WvalT, b_val, p_value_h, CDIM, CDIM, 0,
        nullptr, nullptr, nullptr, nullptr, 0);
    cudaEventRecord(evVal0, 0);

    // stream B (s1): concat -> offaw (reads query f32 directly) -> transposes -> value P1
    concat_t_kernel<<<(128 * CDIM + 255) / 256, 256, 0, s1>>>(W_off, b_off, W_aw, b_aw);
    gemm_h_kernel<128, 0, 3, 1><<<dim3(1, MTOK / BM), 256, SMEM_128_3, s1>>>(
        (const __half*)query, p_WcatT, p_bcat, p_offaw, NOFFAW, CDIM, 0,
        nullptr, nullptr, nullptr, nullptr, 0);
    cudaEventRecord(evB, s1);
    transpose_h_kernel<<<dim3(CDIM / 32, CDIM / 32), tb, 0, s1>>>(W_out, p_WoutT, CDIM, CDIM);
    transpose_h_kernel<<<dim3(DFF / 32,  CDIM / 32), tb, 0, s1>>>(W1, p_W1T, CDIM, DFF);
    transpose_h_kernel<<<dim3(CDIM / 32, DFF / 32),  tb, 0, s1>>>(W2, p_W2T, DFF, CDIM);
    cudaEventRecord(evC, s1);
    cudaStreamWaitEvent(s1, evW, 0);
    gemm_h_kernel<128, 1, 3, 1><<<dim3(2, VAL_MB1), 256, SMEM_128_3, s1>>>(
        (const __half*)src, p_WvalT, b_val, p_value_h, CDIM, CDIM, 0,
        nullptr, nullptr, nullptr, nullptr, VAL_ROW1);

    // ---- back half, two row-chunks pipelined across the two streams ----
    const int MB0 = 313, MB1 = 312;            // tokens [0,40064) / [40064,80000)
    const int MBc[2]  = {MB0, MB1};
    const int ROWc[2] = {0, MB0 * BM};
    cudaStream_t st[2] = {(cudaStream_t)0, s1};

    cudaStreamWaitEvent(0, evB, 0);            // chunk0 sampler needs offaw
    cudaStreamWaitEvent(s1, evVal0, 0);        // chunk1 sampler needs value P0

    for (int c = 0; c < 2; ++c) {
        cudaStream_t s = st[c];
        const int mb = MBc[c], row0 = ROWc[c];
        sample_kernel<<<mb * BM / 8, 256, 0, s>>>(refp, p_attn_h, row0);
        if (c == 0) cudaStreamWaitEvent(0, evC, 0);   // weights needed from here on
        // W_out + residual(query f32) + LN1 -> q2_h (fp16 only)
        gemm_h_kernel<256, 2, 4, 0><<<dim3(1, mb), 256, SMEM_256_4, s>>>(
            p_attn_h, p_WoutT, b_out, nullptr, CDIM, CDIM, 0,
            query, g1, be1, p_q2_h, row0);
        // FFN1 (relu, fp16 out)
        gemm_h_kernel<128, 1, 3, 0><<<dim3(DFF / 128, mb), 256, SMEM_128_3, s>>>(
            p_q2_h, p_W1T, b1, p_ffn_h, DFF, CDIM, 1,
            nullptr, nullptr, nullptr, nullptr, row0);
        // FFN2 + residual(q2_h fp16) + LN2 -> final f32 out
        gemm_h_kernel<256, 3, 4, 0><<<dim3(1, mb), 256, SMEM_256_4, s>>>(
            p_ffn_h, p_W2T, b2, out, CDIM, DFF, 0,
            (const float*)p_q2_h, g2, be2, nullptr, row0);
    }

    // join s1 back to the origin stream (capture requires it)
    cudaEventRecord(evD, s1);
    cudaStreamWaitEvent(0, evD, 0);
}